// round 3
// baseline (speedup 1.0000x reference)
#include <cuda_runtime.h>
#include <cuda_bf16.h>
#include <math.h>

#define N_POINTS 8192
#define PAIR_BLOCKS (N_POINTS / 2)      // 4096 balanced row-pairs
#define PAIR_THREADS 256
#define EDGE_BLOCKS 256
#define EDGE_THREADS 256
#define FIN_THREADS 1024

// Scratch (no allocations allowed; __device__ arrays are the sanctioned pattern).
// No atomics anywhere — each block writes exactly one slot.
__device__ double g_pair_partial[PAIR_BLOCKS];
__device__ float  g_s1_partial[EDGE_BLOCKS];
__device__ float  g_s2_partial[EDGE_BLOCKS];

__device__ __forceinline__ float frcp_approx(float x) {
    float y;
    asm("rcp.approx.f32 %0, %1;" : "=f"(y) : "f"(x));
    return y;
}

// Block reduce a float; returns full sum on thread 0 (valid only there).
__device__ __forceinline__ float block_reduce(float v) {
    #pragma unroll
    for (int off = 16; off > 0; off >>= 1)
        v += __shfl_xor_sync(0xFFFFFFFFu, v, off);
    __shared__ float warp_sums[32];
    int lane = threadIdx.x & 31;
    int wid  = threadIdx.x >> 5;
    if (lane == 0) warp_sums[wid] = v;
    __syncthreads();
    float s = 0.0f;
    if (wid == 0) {
        int nwarps = (blockDim.x + 31) >> 5;
        s = (lane < nwarps) ? warp_sums[lane] : 0.0f;
        #pragma unroll
        for (int off = 16; off > 0; off >>= 1)
            s += __shfl_xor_sync(0xFFFFFFFFu, s, off);
    }
    return s;
}

// One block per balanced row-pair: rows a and b = N-1-a.
// Row a does j in (a, N); row b does j in (b, N). Terms/block = N-1 exactly.
__global__ void __launch_bounds__(PAIR_THREADS, 8)
pair_kernel(const float2* __restrict__ pts) {
    int a = blockIdx.x;
    int b = N_POINTS - 1 - a;

    float2 pa = pts[a];
    float2 pb = pts[b];

    float s = 0.0f;

    for (int j = a + 1 + threadIdx.x; j < N_POINTS; j += PAIR_THREADS) {
        float2 pj = pts[j];
        float dx = pa.x - pj.x;
        float dy = pa.y - pj.y;
        float d = fmaf(dy, dy, fmaf(dx, dx, 1.0f));
        s += frcp_approx(d);
    }
    for (int j = b + 1 + threadIdx.x; j < N_POINTS; j += PAIR_THREADS) {
        float2 pj = pts[j];
        float dx = pb.x - pj.x;
        float dy = pb.y - pj.y;
        float d = fmaf(dy, dy, fmaf(dx, dx, 1.0f));
        s += frcp_approx(d);
    }

    float total = block_reduce(s);
    if (threadIdx.x == 0) g_pair_partial[blockIdx.x] = (double)total;
}

__global__ void __launch_bounds__(EDGE_THREADS)
edge_kernel(const float* __restrict__ pij,
            const int* __restrict__ ei,
            const int* __restrict__ ej,
            const float2* __restrict__ pts,
            int n_edges) {
    float s1 = 0.0f;
    float s2 = 0.0f;
    int stride = gridDim.x * blockDim.x;
    for (int e = blockIdx.x * blockDim.x + threadIdx.x; e < n_edges; e += stride) {
        int ia = ei[e];
        int ja = ej[e];
        float p = pij[e];
        float2 xi = pts[ia];
        float2 xj = pts[ja];
        float dx = xi.x - xj.x;
        float dy = xi.y - xj.y;
        // num = 1/(2 + d2);  p*(log p - log num) = p*log(p*(2+d2))
        float d = fmaf(dy, dy, fmaf(dx, dx, 2.0f));
        s1 += p * __logf(p * d);
        s2 += p;
    }
    float t1 = block_reduce(s1);
    __syncthreads();                 // shared buffer in block_reduce is reused
    float t2 = block_reduce(s2);
    if (threadIdx.x == 0) {
        g_s1_partial[blockIdx.x] = t1;
        g_s2_partial[blockIdx.x] = t2;
    }
}

// Single block: reduce all partials, compute KL = s1 + log(part)*s2.
__global__ void __launch_bounds__(FIN_THREADS)
finish_kernel(float* __restrict__ out) {
    int tid = threadIdx.x;

    double ps = 0.0;
    for (int k = tid; k < PAIR_BLOCKS; k += FIN_THREADS)
        ps += g_pair_partial[k];

    float f1 = 0.0f, f2 = 0.0f;
    if (tid < EDGE_BLOCKS) { f1 = g_s1_partial[tid]; f2 = g_s2_partial[tid]; }

    __shared__ double sd[FIN_THREADS];
    __shared__ float  s1buf[FIN_THREADS];
    __shared__ float  s2buf[FIN_THREADS];
    sd[tid] = ps; s1buf[tid] = f1; s2buf[tid] = f2;
    __syncthreads();
    for (int off = FIN_THREADS / 2; off > 0; off >>= 1) {
        if (tid < off) {
            sd[tid]   += sd[tid + off];
            s1buf[tid]+= s1buf[tid + off];
            s2buf[tid]+= s2buf[tid + off];
        }
        __syncthreads();
    }
    if (tid == 0) {
        double part = 2.0 * sd[0];   // diagonal cancels the -n_diag exactly
        out[0] = (float)((double)s1buf[0] + log(part) * (double)s2buf[0]);
    }
}

extern "C" void kernel_launch(void* const* d_in, const int* in_sizes, int n_in,
                              void* d_out, int out_size) {
    const float*  pij = (const float*)d_in[0];
    const int*    ei  = (const int*)d_in[1];    // jax w/o x64: int64 request -> int32 arrays
    const int*    ej  = (const int*)d_in[2];
    const float2* pts = (const float2*)d_in[3];
    float*        out = (float*)d_out;
    int n_edges = in_sizes[0];

    pair_kernel<<<PAIR_BLOCKS, PAIR_THREADS>>>(pts);
    edge_kernel<<<EDGE_BLOCKS, EDGE_THREADS>>>(pij, ei, ej, pts, n_edges);
    finish_kernel<<<1, FIN_THREADS>>>(out);
}

// round 4
// speedup vs baseline: 1.0691x; 1.0691x over previous
#include <cuda_runtime.h>
#include <cuda_bf16.h>
#include <math.h>

#define N_POINTS 8192
#define TI 1024            // i-tile per block
#define TJ 256             // j-tile per block
#define THREADS 256
#define IPT 4              // i's per thread = TI/THREADS
#define NB (N_POINTS / TJ) // 32 j-chunks
#define PAIR_TILES 144     // sum_{a=0}^{7} (32 - 4a)
#define EDGE_BLKS 64
#define TOTAL_BLKS (PAIR_TILES + EDGE_BLKS)
#define FIN_THREADS 256

// Scratch: one slot per block, no atomics.
__device__ double g_pair_partial[PAIR_TILES];
__device__ float  g_s1_partial[EDGE_BLKS];
__device__ float  g_s2_partial[EDGE_BLKS];

__device__ __forceinline__ float frcp_approx(float x) {
    float y;
    asm("rcp.approx.f32 %0, %1;" : "=f"(y) : "f"(x));
    return y;
}

// Block reduce; full sum valid on thread 0 only.
__device__ __forceinline__ float block_reduce(float v) {
    #pragma unroll
    for (int off = 16; off > 0; off >>= 1)
        v += __shfl_xor_sync(0xFFFFFFFFu, v, off);
    __shared__ float warp_sums[8];
    int lane = threadIdx.x & 31;
    int wid  = threadIdx.x >> 5;
    if (lane == 0) warp_sums[wid] = v;
    __syncthreads();
    float s = 0.0f;
    if (wid == 0) {
        s = (lane < (THREADS >> 5)) ? warp_sums[lane] : 0.0f;
        #pragma unroll
        for (int off = 4; off > 0; off >>= 1)
            s += __shfl_xor_sync(0xFFFFFFFFu, s, off);
    }
    return s;
}

// Fused kernel: blocks [0, PAIR_TILES) do triangle tiles; rest do edges.
__global__ void __launch_bounds__(THREADS)
main_kernel(const float2* __restrict__ pts,
            const float* __restrict__ pij,
            const int* __restrict__ ei,
            const int* __restrict__ ej,
            int n_edges) {
    if (blockIdx.x < PAIR_TILES) {
        // ---- pair phase: tile (a, b), i in [1024a,1024a+1024), j in [256b,256b+256)
        int rem = blockIdx.x, a = 0;
        while (rem >= NB - 4 * a) { rem -= NB - 4 * a; a++; }
        int b = 4 * a + rem;
        bool masked = (b < 4 * a + 4);   // tile straddles the diagonal

        __shared__ float4 feat[TJ];
        int jBase = b * TJ;
        {
            float2 pj = pts[jBase + threadIdx.x];
            feat[threadIdx.x] = make_float4(
                -2.0f * pj.x, -2.0f * pj.y,
                fmaf(pj.x, pj.x, fmaf(pj.y, pj.y, 1.0f)), 0.0f);
        }
        __syncthreads();

        int iBase = a * TI;
        float xi[IPT], yi[IPT], ci[IPT];
        int   ii[IPT];
        #pragma unroll
        for (int k = 0; k < IPT; k++) {
            int i = iBase + threadIdx.x + THREADS * k;
            float2 p = pts[i];
            xi[k] = p.x; yi[k] = p.y;
            ci[k] = fmaf(p.x, p.x, p.y * p.y);
            ii[k] = i;
        }

        float acc0 = 0.0f, acc1 = 0.0f;
        if (!masked) {
            #pragma unroll 8
            for (int jj = 0; jj < TJ; jj++) {
                float4 f = feat[jj];
                float d0 = fmaf(yi[0], f.y, fmaf(xi[0], f.x, f.z)) + ci[0];
                float d1 = fmaf(yi[1], f.y, fmaf(xi[1], f.x, f.z)) + ci[1];
                float d2 = fmaf(yi[2], f.y, fmaf(xi[2], f.x, f.z)) + ci[2];
                float d3 = fmaf(yi[3], f.y, fmaf(xi[3], f.x, f.z)) + ci[3];
                acc0 = fmaf(d0 + d1, frcp_approx(d0 * d1), acc0);
                acc1 = fmaf(d2 + d3, frcp_approx(d2 * d3), acc1);
            }
        } else {
            #pragma unroll 4
            for (int jj = 0; jj < TJ; jj++) {
                int j = jBase + jj;
                float4 f = feat[jj];
                float d0 = fmaf(yi[0], f.y, fmaf(xi[0], f.x, f.z)) + ci[0];
                float d1 = fmaf(yi[1], f.y, fmaf(xi[1], f.x, f.z)) + ci[1];
                float d2 = fmaf(yi[2], f.y, fmaf(xi[2], f.x, f.z)) + ci[2];
                float d3 = fmaf(yi[3], f.y, fmaf(xi[3], f.x, f.z)) + ci[3];
                d0 = (ii[0] < j) ? d0 : 1e12f;   // 1/1e12 contributes ~0
                d1 = (ii[1] < j) ? d1 : 1e12f;
                d2 = (ii[2] < j) ? d2 : 1e12f;
                d3 = (ii[3] < j) ? d3 : 1e12f;
                acc0 = fmaf(d0 + d1, frcp_approx(d0 * d1), acc0);
                acc1 = fmaf(d2 + d3, frcp_approx(d2 * d3), acc1);
            }
        }
        float total = block_reduce(acc0 + acc1);
        if (threadIdx.x == 0) g_pair_partial[blockIdx.x] = (double)total;
    } else {
        // ---- edge phase
        int eb = blockIdx.x - PAIR_TILES;
        float s1 = 0.0f, s2 = 0.0f;
        int stride = EDGE_BLKS * THREADS;
        for (int e = eb * THREADS + threadIdx.x; e < n_edges; e += stride) {
            int ia = ei[e];
            int ja = ej[e];
            float p = pij[e];
            float2 xa = pts[ia];
            float2 xb = pts[ja];
            float dx = xa.x - xb.x;
            float dy = xa.y - xb.y;
            float d = fmaf(dy, dy, fmaf(dx, dx, 2.0f));   // D + ||xi-xj||^2
            s1 += p * __logf(p * d);                      // p*(log p + log(2+d2))
            s2 += p;
        }
        float t1 = block_reduce(s1);
        __syncthreads();
        float t2 = block_reduce(s2);
        if (threadIdx.x == 0) {
            g_s1_partial[eb] = t1;
            g_s2_partial[eb] = t2;
        }
    }
}

__global__ void __launch_bounds__(FIN_THREADS)
finish_kernel(float* __restrict__ out) {
    int tid = threadIdx.x;
    double ps = 0.0;
    for (int k = tid; k < PAIR_TILES; k += FIN_THREADS)
        ps += g_pair_partial[k];
    float f1 = 0.0f, f2 = 0.0f;
    if (tid < EDGE_BLKS) { f1 = g_s1_partial[tid]; f2 = g_s2_partial[tid]; }

    __shared__ double sd[FIN_THREADS];
    __shared__ float  s1buf[FIN_THREADS];
    __shared__ float  s2buf[FIN_THREADS];
    sd[tid] = ps; s1buf[tid] = f1; s2buf[tid] = f2;
    __syncthreads();
    for (int off = FIN_THREADS / 2; off > 0; off >>= 1) {
        if (tid < off) {
            sd[tid]    += sd[tid + off];
            s1buf[tid] += s1buf[tid + off];
            s2buf[tid] += s2buf[tid + off];
        }
        __syncthreads();
    }
    if (tid == 0) {
        double part = 2.0 * sd[0];   // diagonal cancels -n_diag exactly
        out[0] = (float)((double)s1buf[0] + log(part) * (double)s2buf[0]);
    }
}

extern "C" void kernel_launch(void* const* d_in, const int* in_sizes, int n_in,
                              void* d_out, int out_size) {
    const float*  pij = (const float*)d_in[0];
    const int*    ei  = (const int*)d_in[1];   // jax w/o x64: int32 on device
    const int*    ej  = (const int*)d_in[2];
    const float2* pts = (const float2*)d_in[3];
    float*        out = (float*)d_out;
    int n_edges = in_sizes[0];

    main_kernel<<<TOTAL_BLKS, THREADS>>>(pts, pij, ei, ej, n_edges);
    finish_kernel<<<1, FIN_THREADS>>>(out);
}